// round 5
// baseline (speedup 1.0000x reference)
#include <cuda_runtime.h>
#include <cstdint>

// Shapes fixed by the dataset:
// log_belief: (N=4, Cin=4, H=128, W=128)  f32
// log_kernel: (N=4, Cin=4, 100, H, W)     f32   (100 = Cout*K*K = 4*25)
// out:        (N=4, Cout=4, H, W)         f32
#define HW      16384
#define NEGBIG  (-1e30f)
#define CSHIFT  12.0f
#define ROWF    136            // padded row: [4 pad][128 data][4 pad] floats
#define P0      4              // interior float offset (16B aligned for cp.async)
#define NROWS   120            // 100 lk rows (tap*4+ci) + 20 lb rows (ky*4+ci)
#define SMEM_BYTES (NROWS * ROWF * 4)   // 65280

__device__ __forceinline__ void cp16(uint32_t dst, const float* src) {
    asm volatile("cp.async.cg.shared.global [%0], [%1], 16;\n"
                 :: "r"(dst), "l"(src));
}

// One ky stage: wait for its cp.async group, then accumulate 4ci x 5kx terms.
template<int KY>
__device__ __forceinline__ void stage(const float* sm, int x, int ky_lo, int ky_hi,
                                      float& s0, float& s1, float& s2, float& s3)
{
    asm volatile("cp.async.wait_group %0;\n" :: "n"(4 - KY));
    __syncthreads();
    if (KY < ky_lo || KY > ky_hi) return;   // warp-uniform; no further syncs below

    #pragma unroll
    for (int ci = 0; ci < 4; ci++) {
        const float* lbr = sm + (100 + KY * 4 + ci) * ROWF;
        #pragma unroll
        for (int kx = 0; kx < 5; kx++) {
            const float* lkr = sm + ((KY * 5 + kx) * 4 + ci) * ROWF;
            int idx = x + 6 - kx;           // = xi + P0, xi = x+2-kx; pads kill OOB
            float e = __expf(lbr[idx] + lkr[idx] + CSHIFT);
            if      (kx == 0) s0 += e;
            else if (kx == 1) s1 += e;
            else if (kx == 2) s2 += e;
            else if (kx == 3) s3 += e;
            else              s0 += e;
        }
    }
}

__global__ __launch_bounds__(128)
void propagate_lse_v5(const float* __restrict__ lb_g,
                      const float* __restrict__ lk_g,
                      float* __restrict__ out)
{
    extern __shared__ float sm[];
    const int tid = threadIdx.x;
    const int bid = blockIdx.x;                 // (n, co, yo)
    const int n  = bid >> 9;
    const int co = (bid >> 7) & 3;
    const int yo = bid & 127;

    uint32_t smb = (uint32_t)__cvta_generic_to_shared(sm);

    // ---- pad init: 120 rows x 8 pad floats (lb rows -> NEGBIG, lk rows -> 0) ----
    for (int i = tid; i < NROWS * 8; i += 128) {
        int row = i >> 3, e = i & 7;
        sm[row * ROWF + (e < 4 ? e : 128 + e)] = (row >= 100) ? NEGBIG : 0.0f;
    }
    // visibility covered by the __syncthreads inside stage<0>

    // ---- issue all 5 ky stages of async copies (one commit group per stage) ----
    // Per stage: 640 lk chunks (20 rows x 32) + 128 lb chunks (4 rows x 32) = 768
    // = 6 chunks of 16B per thread per stage.
    #pragma unroll
    for (int ky = 0; ky < 5; ky++) {
        int yi = yo + 2 - ky;
        yi = yi < 0 ? 0 : (yi > 127 ? 127 : yi);   // clamp; invalid ky skipped in compute
        #pragma unroll
        for (int k = 0; k < 6; k++) {
            int c = tid + (k << 7);                // 0..767
            if (c < 640) {
                int r = c >> 5, q = c & 31;        // r: kx*4+ci
                int kx = r >> 2, ci = r & 3;
                const float* src = lk_g
                    + (size_t)((n*4 + ci)*100 + co*25 + ky*5 + kx) * HW
                    + yi * 128 + q * 4;
                int drow = (ky*5 + kx)*4 + ci;
                cp16(smb + (uint32_t)(drow * ROWF + P0 + q*4) * 4, src);
            } else {
                int c2 = c - 640;
                int ci = c2 >> 5, q = c2 & 31;
                const float* src = lb_g + (size_t)(n*4 + ci) * HW + yi * 128 + q * 4;
                int drow = 100 + ky*4 + ci;
                cp16(smb + (uint32_t)(drow * ROWF + P0 + q*4) * 4, src);
            }
        }
        asm volatile("cp.async.commit_group;\n");
    }

    // ---- compute: thread owns output column x = tid ----
    const int ky_lo = yo > 125 ? yo - 125 : 0;
    const int ky_hi = yo < 2 ? yo + 2 : 4;
    float s0 = 0.f, s1 = 0.f, s2 = 0.f, s3 = 0.f;

    stage<0>(sm, tid, ky_lo, ky_hi, s0, s1, s2, s3);
    stage<1>(sm, tid, ky_lo, ky_hi, s0, s1, s2, s3);
    stage<2>(sm, tid, ky_lo, ky_hi, s0, s1, s2, s3);
    stage<3>(sm, tid, ky_lo, ky_hi, s0, s1, s2, s3);
    stage<4>(sm, tid, ky_lo, ky_hi, s0, s1, s2, s3);

    float sum = (s0 + s1) + (s2 + s3);
    out[(size_t)((n*4 + co)*128 + yo) * 128 + tid] = __logf(sum) - CSHIFT;
}

extern "C" void kernel_launch(void* const* d_in, const int* in_sizes, int n_in,
                              void* d_out, int out_size)
{
    const float* lb = (const float*)d_in[0];
    const float* lk = (const float*)d_in[1];
    float* out = (float*)d_out;
    cudaFuncSetAttribute(propagate_lse_v5,
                         cudaFuncAttributeMaxDynamicSharedMemorySize, SMEM_BYTES);
    // 2048 blocks: one per (n, co, yo) output row
    propagate_lse_v5<<<2048, 128, SMEM_BYTES>>>(lb, lk, out);
}

// round 6
// speedup vs baseline: 1.2995x; 1.2995x over previous
#include <cuda_runtime.h>

// Shapes fixed by the dataset:
// log_belief: (N=4, Cin=4, H=128, W=128)  f32
// log_kernel: (N=4, Cin=4, 100, H, W)     f32   (100 = Cout*K*K = 4*25)
// out:        (N=4, Cout=4, H, W)         f32
#define HW     16384
#define NEGBIG (-1e30f)
#define CSHIFT 12.0f

template<int D>
__device__ __forceinline__ void lkwin(const float4* __restrict__ row,
                                      int t, int tm1, int tp1,
                                      float& r0, float& r1, float& r2, float& r3)
{
    if constexpr (D == 0) {
        float4 q = __ldcs(row + t);
        r0 = q.x; r1 = q.y; r2 = q.z; r3 = q.w;
    } else if constexpr (D == 1) {
        float4 q0 = __ldcs(row + t), q1 = __ldcs(row + tp1);
        r0 = q0.y; r1 = q0.z; r2 = q0.w; r3 = q1.x;
    } else if constexpr (D == 2) {
        float4 q0 = __ldcs(row + t), q1 = __ldcs(row + tp1);
        r0 = q0.z; r1 = q0.w; r2 = q1.x; r3 = q1.y;
    } else if constexpr (D == -1) {
        float4 qm = __ldcs(row + tm1), q0 = __ldcs(row + t);
        r0 = qm.w; r1 = q0.x; r2 = q0.y; r3 = q0.z;
    } else { // D == -2
        float4 qm = __ldcs(row + tm1), q0 = __ldcs(row + t);
        r0 = qm.z; r1 = qm.w; r2 = q0.x; r3 = q0.y;
    }
}

// Block (256 thr = 8 warps) handles (n, co, 4 consecutive output rows).
// Warp j: local row r = j>>1, ci-group cig = j&1 (channels 2*cig, 2*cig+1).
// The 4-row tile makes each lk plane's reads 4-8 consecutive rows (2-4 KB
// contiguous, issued near-simultaneously) instead of isolated 512B rows.
__global__ __launch_bounds__(256, 4)
void propagate_lse_v6(const float* __restrict__ lb_g,
                      const float* __restrict__ lk_g,
                      float* __restrict__ out)
{
    __shared__ float part[8][128];

    int bid = blockIdx.x;          // 0..511 = (n, co, ytile)
    int n   = bid >> 7;
    int co  = (bid >> 5) & 3;
    int Y   = (bid & 31) * 4;      // first output row of tile

    int j   = threadIdx.x >> 5;    // warp in block
    int t   = threadIdx.x & 31;    // lane: owns outputs xo = 4t..4t+3
    int r   = j >> 1;
    int cig = j & 1;
    int yo  = Y + r;

    int tm1 = (t == 0)  ? 0  : t - 1;
    int tp1 = (t == 31) ? 31 : t + 1;

    float s0 = 0.f, s1 = 0.f, s2 = 0.f, s3 = 0.f;

    #pragma unroll 1
    for (int ky = 0; ky < 5; ky++) {
        int yi = yo + 2 - ky;
        if ((unsigned)yi >= 128u) continue;   // warp-uniform

        #pragma unroll 1
        for (int cc = 0; cc < 2; cc++) {
            int ci = cig * 2 + cc;

            // ---- lb window: absolute x = 4t + o, o = -2..5 -> w0..w7 ----
            const float4* b4 = (const float4*)(lb_g + (size_t)((n*4 + ci)*128 + yi) * 128);
            float4 bm = __ldg(b4 + tm1);
            float4 bc = __ldg(b4 + t);
            float4 bp = __ldg(b4 + tp1);
            float w0 = bm.z, w1 = bm.w;
            float w2 = bc.x, w3 = bc.y, w4 = bc.z, w5 = bc.w;
            float w6 = bp.x, w7 = bp.y;
            if (t == 0)  { w0 = NEGBIG; w1 = NEGBIG; }
            if (t == 31) { w6 = NEGBIG; w7 = NEGBIG; }

            const float* plane0 = lk_g
                + (size_t)((n*4 + ci)*100 + co*25 + ky*5) * HW
                + (size_t)yi * 128;

            float r0, r1, r2, r3;
            // kx = 0 (D=+2): lb offsets j+2 -> w4..w7
            lkwin<2>((const float4*)(plane0 + 0*HW), t, tm1, tp1, r0, r1, r2, r3);
            s0 += __expf(w4 + r0 + CSHIFT);
            s1 += __expf(w5 + r1 + CSHIFT);
            s2 += __expf(w6 + r2 + CSHIFT);
            s3 += __expf(w7 + r3 + CSHIFT);
            // kx = 1 (D=+1): w3..w6
            lkwin<1>((const float4*)(plane0 + 1*HW), t, tm1, tp1, r0, r1, r2, r3);
            s0 += __expf(w3 + r0 + CSHIFT);
            s1 += __expf(w4 + r1 + CSHIFT);
            s2 += __expf(w5 + r2 + CSHIFT);
            s3 += __expf(w6 + r3 + CSHIFT);
            // kx = 2 (D=0): w2..w5
            lkwin<0>((const float4*)(plane0 + 2*HW), t, tm1, tp1, r0, r1, r2, r3);
            s0 += __expf(w2 + r0 + CSHIFT);
            s1 += __expf(w3 + r1 + CSHIFT);
            s2 += __expf(w4 + r2 + CSHIFT);
            s3 += __expf(w5 + r3 + CSHIFT);
            // kx = 3 (D=-1): w1..w4
            lkwin<-1>((const float4*)(plane0 + 3*HW), t, tm1, tp1, r0, r1, r2, r3);
            s0 += __expf(w1 + r0 + CSHIFT);
            s1 += __expf(w2 + r1 + CSHIFT);
            s2 += __expf(w3 + r2 + CSHIFT);
            s3 += __expf(w4 + r3 + CSHIFT);
            // kx = 4 (D=-2): w0..w3
            lkwin<-2>((const float4*)(plane0 + 4*HW), t, tm1, tp1, r0, r1, r2, r3);
            s0 += __expf(w0 + r0 + CSHIFT);
            s1 += __expf(w1 + r1 + CSHIFT);
            s2 += __expf(w2 + r2 + CSHIFT);
            s3 += __expf(w3 + r3 + CSHIFT);
        }
    }

    // stash per-warp partial exp-sums
    float4 sv; sv.x = s0; sv.y = s1; sv.z = s2; sv.w = s3;
    ((float4*)part[j])[t] = sv;
    __syncthreads();

    // combine ci-groups: 512 outputs (4 rows x 128), 256 threads -> 2 each
    int i = threadIdx.x;
    #pragma unroll
    for (int rr = 0; rr < 2; rr++) {
        int row = i >> 7, col = i & 127;          // local rows 0-1, then 2-3
        int lr = rr * 2 + row;
        float sum = part[lr*2 + 0][col] + part[lr*2 + 1][col];
        out[(size_t)((n*4 + co)*128 + Y + lr) * 128 + col] = __logf(sum) - CSHIFT;
    }
}

extern "C" void kernel_launch(void* const* d_in, const int* in_sizes, int n_in,
                              void* d_out, int out_size)
{
    const float* lb = (const float*)d_in[0];
    const float* lk = (const float*)d_in[1];
    float* out = (float*)d_out;
    // 512 blocks: (n, co, ytile of 4 rows) -> one full-chip wave at 4 blocks/SM
    propagate_lse_v6<<<512, 256>>>(lb, lk, out);
}